// round 1
// baseline (speedup 1.0000x reference)
#include <cuda_runtime.h>

// Problem shapes (fixed by the dataset):
//   node_rep      [N=400000, D=300] f32
//   batch         [N] i32, SORTED ascending in [0, B)
//   primary_label [N] i32 in {-1, 0}
//   num_graphs    B = 4096 (scalar input, ignored; grid is hardcoded)
//   out           [N, 2D=600] f32 = [node_rep | cond_pool[batch]]
//
// One CTA per graph. batch sorted => graph g owns contiguous rows [s, e),
// found via two binary searches. Pass 1 streams rows: copy left half of out,
// accumulate condition-row sums in registers (column ownership, no atomics).
// Reduce across y-lanes in shared, apply gate (last node of graph has label -1)
// and 1/max(cnt,1). Pass 2 broadcasts the pooled vector to the right half.

#define DDIM 300
#define D4   75          // D / 4 float4 per input row
#define OUT4 150         // 2D / 4 float4 per output row
#define BY   4           // row lanes per block

__global__ __launch_bounds__(D4 * BY)
void reactant_centre_kernel(const float4* __restrict__ x4,     // [N, 75]
                            const int*    __restrict__ batch,  // [N]
                            const int*    __restrict__ label,  // [N]
                            float4*       __restrict__ out4,   // [N, 150]
                            int n)
{
    const int g  = blockIdx.x;
    const int c4 = threadIdx.x;   // 0..74  (float4 column)
    const int ry = threadIdx.y;   // 0..3   (row lane)
    const int tid = ry * D4 + c4;

    __shared__ int    s_se[2];
    __shared__ float4 s_acc[BY][D4];
    __shared__ int    s_cnt[BY];
    __shared__ float4 s_pool[D4];

    // Two lower_bound searches: start of graph g and start of graph g+1.
    if (tid < 2) {
        int target = g + tid;
        int lo = 0, hi = n;
        while (lo < hi) {
            int mid = (lo + hi) >> 1;
            if (batch[mid] < target) lo = mid + 1; else hi = mid;
        }
        s_se[tid] = lo;
    }
    __syncthreads();
    const int s = s_se[0];
    const int e = s_se[1];

    // Pass 1: stream rows. Copy left half, accumulate condition rows.
    float4 acc = make_float4(0.f, 0.f, 0.f, 0.f);
    int cnt = 0;
    for (int r = s + ry; r < e; r += BY) {
        float4 v = x4[(long)r * D4 + c4];
        out4[(long)r * OUT4 + c4] = v;
        if (label[r] == -1) {
            acc.x += v.x; acc.y += v.y; acc.z += v.z; acc.w += v.w;
            cnt++;
        }
    }
    s_acc[ry][c4] = acc;
    if (c4 == 0) s_cnt[ry] = cnt;
    __syncthreads();

    // Gate: only pool if the LAST node of the graph is a condition node.
    const bool flag = (e > s) && (label[e - 1] == -1);

    if (ry == 0) {
        float4 a = s_acc[0][c4];
        float4 b = s_acc[1][c4];
        float4 c = s_acc[2][c4];
        float4 d = s_acc[3][c4];
        float4 tot = make_float4(a.x + b.x + c.x + d.x,
                                 a.y + b.y + c.y + d.y,
                                 a.z + b.z + c.z + d.z,
                                 a.w + b.w + c.w + d.w);
        float tc  = (float)(s_cnt[0] + s_cnt[1] + s_cnt[2] + s_cnt[3]);
        float inv = flag ? (1.0f / fmaxf(tc, 1.0f)) : 0.0f;
        s_pool[c4] = make_float4(tot.x * inv, tot.y * inv,
                                 tot.z * inv, tot.w * inv);
    }
    __syncthreads();

    // Pass 2: broadcast pooled vector into right half of every row.
    const float4 p = s_pool[c4];
    for (int r = s + ry; r < e; r += BY) {
        out4[(long)r * OUT4 + D4 + c4] = p;
    }
}

extern "C" void kernel_launch(void* const* d_in, const int* in_sizes, int n_in,
                              void* d_out, int out_size)
{
    const float* node_rep = (const float*)d_in[0];
    const int*   batch    = (const int*)d_in[1];
    const int*   label    = (const int*)d_in[2];
    (void)n_in; (void)out_size;

    const int n = in_sizes[1];        // N from batch array
    const int B = 4096;               // num_graphs (fixed problem shape)

    dim3 block(D4, BY);               // 75 x 4 = 300 threads
    reactant_centre_kernel<<<B, block>>>((const float4*)node_rep, batch, label,
                                         (float4*)d_out, n);
}